// round 1
// baseline (speedup 1.0000x reference)
#include <cuda_runtime.h>

// Sparse BasicBlock (stride 1, no downsample), fused into 2 conv kernels.
//
// Exact algebraic reduction of the reference (mask binary, mask_dilate>=mask):
//   g   = mask * vector * relu(bn1(conv1(x * mask_dilate)))
//   out = relu(x + mask * bn2(conv2(g)))

namespace {
constexpr int B = 32, C = 256, H = 56, W = 56;
constexpr int HW  = H * W;
constexpr int CHW = C * HW;
constexpr int CO_T = 64;   // output channels per block
constexpr int CI_T = 8;    // input-channel chunk staged in smem
constexpr float EPS = 1e-5f;
}

// 103 MB intermediate (allocs forbidden -> __device__ global scratch)
__device__ float g_scratch[(size_t)B * CHW];

// STAGE==1: in = x*mask_dilate, epilogue writes g_scratch
// STAGE==2: in = g_scratch,     epilogue writes out (residual + relu)
template <int STAGE>
__global__ __launch_bounds__(256)
void sparse_block_conv(const float* __restrict__ x,
                       const float* __restrict__ premask,   // mask_dilate (stage 1 only)
                       const float* __restrict__ wgt,       // [C][C][3][3]
                       const float* __restrict__ mask,      // [B][1][H][W]
                       const float* __restrict__ vec,       // [B][C] (stage 1 only)
                       const float* __restrict__ bg, const float* __restrict__ bb,
                       const float* __restrict__ bm, const float* __restrict__ bv,
                       float* __restrict__ out)             // stage 2 only
{
    // smem padded for conflict-free compute reads:
    //  in_s row pitch 12 -> the 16 spatial-group addresses land on distinct banks
    //  w_s  row pitch 73 -> the 2 co-values per warp land on distinct banks
    __shared__ float in_s[CI_T][10][12];
    __shared__ float w_s[CO_T][CI_T * 9 + 1];

    const int b    = blockIdx.z;
    const int cog  = blockIdx.y;          // 0..3 (64-channel group)
    const int tile = blockIdx.x;          // 0..48 (7x7 tiles of 8x8, 56=7*8 exact)
    const int ty0  = (tile / 7) * 8;
    const int tx0  = (tile % 7) * 8;

    const int t   = threadIdx.x;
    const int g   = t & 15;               // spatial 2x2 group: 4x4 grid of groups
    const int cth = t >> 4;               // 0..15, owns 4 consecutive out-channels
    const int gy  = g >> 2, gx = g & 3;

    const float* in_base = (STAGE == 1) ? (x + (size_t)b * CHW)
                                        : (g_scratch + (size_t)b * CHW);
    const float* pm = (STAGE == 1) ? (premask + (size_t)b * HW) : nullptr;

    float acc[4][2][2];
#pragma unroll
    for (int j = 0; j < 4; ++j)
#pragma unroll
        for (int dy = 0; dy < 2; ++dy)
#pragma unroll
            for (int dx = 0; dx < 2; ++dx) acc[j][dy][dx] = 0.f;

    for (int ci0 = 0; ci0 < C; ci0 += CI_T) {
        __syncthreads();
        // ---- stage input tile: CI_T x 10 x 10 (halo, zero-padded), fused premask
        for (int e = t; e < CI_T * 100; e += 256) {
            int ci = e / 100, r = e % 100;
            int ry = r / 10, rx = r % 10;
            int iy = ty0 + ry - 1, ix = tx0 + rx - 1;
            float v = 0.f;
            if (iy >= 0 && iy < H && ix >= 0 && ix < W) {
                v = in_base[(size_t)(ci0 + ci) * HW + iy * W + ix];
                if (STAGE == 1) v *= pm[iy * W + ix];
            }
            in_s[ci][ry][rx] = v;
        }
        // ---- stage weights: CO_T x CI_T x 9 (gmem [O][I][3][3] is contiguous in (I,k))
        for (int e = t; e < CO_T * CI_T * 9; e += 256) {
            int co = e / (CI_T * 9), r = e % (CI_T * 9);
            w_s[co][r] = wgt[((size_t)(cog * CO_T + co) * C + ci0) * 9 + r];
        }
        __syncthreads();

#pragma unroll
        for (int ci = 0; ci < CI_T; ++ci) {
            float iv[4][4];                      // 4x4 patch -> 2x2 outputs, 3x3 taps
#pragma unroll
            for (int dy = 0; dy < 4; ++dy)
#pragma unroll
                for (int dx = 0; dx < 4; ++dx)
                    iv[dy][dx] = in_s[ci][gy * 2 + dy][gx * 2 + dx];
#pragma unroll
            for (int j = 0; j < 4; ++j) {
                const float* wrow = &w_s[cth * 4 + j][ci * 9];
#pragma unroll
                for (int r = 0; r < 3; ++r)
#pragma unroll
                    for (int s = 0; s < 3; ++s) {
                        const float w = wrow[r * 3 + s];
                        acc[j][0][0] = fmaf(w, iv[r][s],         acc[j][0][0]);
                        acc[j][0][1] = fmaf(w, iv[r][s + 1],     acc[j][0][1]);
                        acc[j][1][0] = fmaf(w, iv[r + 1][s],     acc[j][1][0]);
                        acc[j][1][1] = fmaf(w, iv[r + 1][s + 1], acc[j][1][1]);
                    }
            }
        }
    }

    // ---- epilogue: BN (+relu) + mask (+vector / +residual)
#pragma unroll
    for (int j = 0; j < 4; ++j) {
        const int cg = cog * CO_T + cth * 4 + j;
        const float inv  = rsqrtf(bv[cg] + EPS) * bg[cg];
        const float beta = bb[cg] - bm[cg] * inv;
        float vscale = 1.f;
        if (STAGE == 1) vscale = vec[b * C + cg];
#pragma unroll
        for (int dy = 0; dy < 2; ++dy)
#pragma unroll
            for (int dx = 0; dx < 2; ++dx) {
                const int y  = ty0 + gy * 2 + dy;
                const int xp = tx0 + gx * 2 + dx;
                const float mk  = mask[(size_t)b * HW + y * W + xp];
                const float bnv = acc[j][dy][dx] * inv + beta;
                const size_t oidx = (size_t)b * CHW + (size_t)cg * HW + y * W + xp;
                if (STAGE == 1) {
                    g_scratch[oidx] = mk * vscale * fmaxf(bnv, 0.f);
                } else {
                    out[oidx] = fmaxf(x[oidx] + mk * bnv, 0.f);
                }
            }
    }
}

extern "C" void kernel_launch(void* const* d_in, const int* in_sizes, int n_in,
                              void* d_out, int out_size) {
    const float* x    = (const float*)d_in[0];
    const float* mask = (const float*)d_in[1];
    const float* md   = (const float*)d_in[2];
    const float* vec  = (const float*)d_in[3];
    const float* w1   = (const float*)d_in[4];
    const float* g1   = (const float*)d_in[5];
    const float* b1   = (const float*)d_in[6];
    const float* m1   = (const float*)d_in[7];
    const float* v1   = (const float*)d_in[8];
    const float* w2   = (const float*)d_in[9];
    const float* g2   = (const float*)d_in[10];
    const float* b2   = (const float*)d_in[11];
    const float* m2   = (const float*)d_in[12];
    const float* v2   = (const float*)d_in[13];
    float* out = (float*)d_out;

    dim3 grid(49, C / CO_T, B);   // 7x7 spatial tiles, 4 channel groups, 32 batch
    sparse_block_conv<1><<<grid, 256>>>(x, md, w1, mask, vec,
                                        g1, b1, m1, v1, nullptr);
    sparse_block_conv<2><<<grid, 256>>>(x, nullptr, w2, mask, nullptr,
                                        g2, b2, m2, v2, out);
}

// round 3
// speedup vs baseline: 3.4124x; 3.4124x over previous
#include <cuda_runtime.h>
#include <cuda_bf16.h>
#include <cstdint>

// Sparse BasicBlock via HMMA (mma.sync bf16, sm_80-compatible path; the remote
// build targets plain sm_103, so tcgen05/.a features are unavailable).
//   g   = mask * vector * relu(bn1(conv1(x * mask_dilate)))
//   out = relu(x + mask * bn2(conv2(g)))
// Implicit GEMM per conv: A = weights (M=128 ch/CTA, prepacked), B = pixels
// (N=128/CTA), K = 2304 in 72 chunks of 32. fp32 ~ bf16 hi/lo split, 3 terms.

namespace {
constexpr int B_ = 32, C_ = 256, H_ = 56, W_ = 56;
constexpr int HW_ = H_ * W_, CHW_ = C_ * HW_;
constexpr float EPS = 1e-5f;

constexpr int PITCH_A = 80;              // 32 bf16 = 64B data + 16B pad
constexpr int PITCH_B = 272;             // 128 bf16 = 256B data + 16B pad
constexpr int A_TILE  = 128 * PITCH_A;   // 10240 B (one matrix)
constexpr int TILE_BYTES = 2 * A_TILE;   // hi+lo weight tile image = 20480 B
constexpr int B_TILE  = 32 * PITCH_B;    // 8704 B

// smem offsets
constexpr int S_AHI = 0;
constexpr int S_ALO = A_TILE;
constexpr int S_BHI = 2 * A_TILE;                // 20480
constexpr int S_BLO = S_BHI + B_TILE;            // 29184
constexpr int S_SC  = S_BLO + B_TILE;            // 37888 (128 f32)
constexpr int S_BI  = S_SC + 512;                // 38400
constexpr int SMEM_BYTES = S_BI + 512;           // 38912 (< 48K static)
}

__device__ float g_scratch[(size_t)B_ * CHW_];                       // 103 MB
__device__ __align__(16) unsigned char wpack[(size_t)288 * TILE_BYTES]; // 5.9 MB

// ---------------- helpers ----------------
__device__ __forceinline__ uint32_t smem_u32(const void* p) {
    uint32_t a;
    asm("{ .reg .u64 t; cvta.to.shared.u64 t, %1; cvt.u32.u64 %0, t; }" : "=r"(a) : "l"(p));
    return a;
}
__device__ __forceinline__ void cp_async16(uint32_t s, const void* g) {
    asm volatile("cp.async.cg.shared.global [%0], [%1], 16;" :: "r"(s), "l"(g));
}
__device__ __forceinline__ void cp_async_wait_all() {
    asm volatile("cp.async.commit_group;\ncp.async.wait_group 0;" ::: "memory");
}
__device__ __forceinline__ void ldsm4(uint32_t* r, uint32_t a) {
    asm volatile("ldmatrix.sync.aligned.m8n8.x4.shared.b16 {%0,%1,%2,%3}, [%4];"
                 : "=r"(r[0]), "=r"(r[1]), "=r"(r[2]), "=r"(r[3]) : "r"(a));
}
__device__ __forceinline__ void ldsm4t(uint32_t* r, uint32_t a) {
    asm volatile("ldmatrix.sync.aligned.m8n8.x4.trans.shared.b16 {%0,%1,%2,%3}, [%4];"
                 : "=r"(r[0]), "=r"(r[1]), "=r"(r[2]), "=r"(r[3]) : "r"(a));
}
__device__ __forceinline__ void mma16816(float* c, const uint32_t* a, const uint32_t* b) {
    asm volatile(
        "mma.sync.aligned.m16n8k16.row.col.f32.bf16.bf16.f32 "
        "{%0,%1,%2,%3}, {%4,%5,%6,%7}, {%8,%9}, {%0,%1,%2,%3};"
        : "+f"(c[0]), "+f"(c[1]), "+f"(c[2]), "+f"(c[3])
        : "r"(a[0]), "r"(a[1]), "r"(a[2]), "r"(a[3]), "r"(b[0]), "r"(b[1]));
}
// -----------------------------------------

// Pre-pack weights [O][I][3][3] fp32 into per-(conv,half,tap,chunk) smem tile
// images: hi matrix [128 rows x 80B pitch] then lo, bf16.
__global__ __launch_bounds__(256) void prepack_kernel(const float* __restrict__ w1,
                                                      const float* __restrict__ w2) {
    size_t idx = (size_t)blockIdx.x * 256 + threadIdx.x;   // 288 * 4096
    int tix = (int)(idx >> 12);
    int e   = (int)(idx & 4095);
    int m = e >> 5, kk = e & 31;
    int chunk = tix & 7, tap = (tix >> 3) % 9;
    int half = (tix / 72) & 1, conv = tix / 144;
    const float* w = conv ? w2 : w1;
    int n_out = half * 128 + m, ci = chunk * 32 + kk;
    float v = w[((size_t)n_out * C_ + ci) * 9 + tap];
    __nv_bfloat16 h = __float2bfloat16(v);
    __nv_bfloat16 l = __float2bfloat16(v - __bfloat162float(h));
    unsigned char* base = wpack + (size_t)tix * TILE_BYTES + m * PITCH_A + kk * 2;
    *(__nv_bfloat16*)base = h;
    *(__nv_bfloat16*)(base + A_TILE) = l;
}

// STAGE 1: in = x*mask_dilate -> g_scratch   STAGE 2: in = g_scratch -> out
template <int STAGE>
__global__ __launch_bounds__(256, 2)
void conv_hmma(const float* __restrict__ x, const float* __restrict__ md,
               const float* __restrict__ mask, const float* __restrict__ vec,
               const float* __restrict__ bg, const float* __restrict__ bb,
               const float* __restrict__ bm, const float* __restrict__ bv,
               float* __restrict__ out)
{
    __shared__ __align__(16) unsigned char sm[SMEM_BYTES];
    const uint32_t sb = smem_u32(sm);
    const int t = threadIdx.x, lane = t & 31, wid = t >> 5;
    const int half = blockIdx.x, blk = blockIdx.y, b = blockIdx.z;
    const int pixbase = blk * 128;

    float* scs = (float*)(sm + S_SC);
    float* bis = (float*)(sm + S_BI);
    if (t < 128) {
        int ch = half * 128 + t;
        float iv = rsqrtf(bv[ch] + EPS) * bg[ch];
        scs[t] = iv;
        bis[t] = bb[ch] - bm[ch] * iv;
    }

    const float* inb = (STAGE == 1) ? x + (size_t)b * CHW_ : g_scratch + (size_t)b * CHW_;
    const float* mdb = (STAGE == 1) ? md + (size_t)b * HW_ : nullptr;

    // B gather geometry: each thread owns one pixel pair for all iters
    const int pp  = (t & 63) * 2;            // local pixel pair base
    const int kk0 = t >> 6;                  // 0..3
    const int pix0 = pixbase + pp, pix1 = pix0 + 1;
    const int py0 = pix0 / W_, px0 = pix0 - py0 * W_;
    const int py1 = pix1 / W_, px1 = pix1 - py1 * W_;

    // warp tiling: 4 (ch) x 2 (pix)
    const int m0 = (wid & 3) * 32;           // channel row base within 128
    const int n0 = (wid >> 2) * 64;          // pixel col base within 128

    float acc[2][8][4];
#pragma unroll
    for (int mt = 0; mt < 2; ++mt)
#pragma unroll
        for (int nt = 0; nt < 8; ++nt)
#pragma unroll
            for (int q = 0; q < 4; ++q) acc[mt][nt][q] = 0.f;

    const int tixbase = ((STAGE - 1) * 2 + half) * 9 * 8;

    for (int tap = 0; tap < 9; ++tap) {
        const int dy = tap / 3 - 1, dx = tap % 3 - 1;
        const int iy0 = py0 + dy, ix0 = px0 + dx;
        const int iy1 = py1 + dy, ix1 = px1 + dx;
        const bool v0 = pix0 < HW_ && (unsigned)iy0 < (unsigned)H_ && (unsigned)ix0 < (unsigned)W_;
        const bool v1 = pix1 < HW_ && (unsigned)iy1 < (unsigned)H_ && (unsigned)ix1 < (unsigned)W_;
        const int sp0 = v0 ? iy0 * W_ + ix0 : 0;
        const int sp1 = v1 ? iy1 * W_ + ix1 : 0;
        float pm0 = 0.f, pm1 = 0.f;
        if (v0) pm0 = (STAGE == 1) ? mdb[sp0] : 1.f;
        if (v1) pm1 = (STAGE == 1) ? mdb[sp1] : 1.f;

        for (int chunk = 0; chunk < 8; ++chunk) {
            __syncthreads();   // previous iter's MMAs done before overwriting tiles

            // ---- A (weights): cp.async copy of the prepacked 20480B tile image
            {
                const unsigned char* g =
                    wpack + (size_t)(tixbase + tap * 8 + chunk) * TILE_BYTES;
#pragma unroll
                for (int i = 0; i < 5; ++i) {
                    int off = (t + 256 * i) * 16;
                    cp_async16(sb + S_AHI + off, g + off);
                }
            }
            // ---- B (pixels): gather + premask + bf16 hi/lo split, conflict-free STS
#pragma unroll
            for (int i = 0; i < 8; ++i) {
                int kk = kk0 + i * 4;
                const float* src = inb + (size_t)(chunk * 32 + kk) * HW_;
                float f0 = v0 ? src[sp0] * pm0 : 0.f;
                float f1 = v1 ? src[sp1] * pm1 : 0.f;
                __nv_bfloat16 h0 = __float2bfloat16(f0), h1 = __float2bfloat16(f1);
                __nv_bfloat16 l0 = __float2bfloat16(f0 - __bfloat162float(h0));
                __nv_bfloat16 l1 = __float2bfloat16(f1 - __bfloat162float(h1));
                uint32_t hp = ((uint32_t)__bfloat16_as_ushort(h1) << 16) | __bfloat16_as_ushort(h0);
                uint32_t lp = ((uint32_t)__bfloat16_as_ushort(l1) << 16) | __bfloat16_as_ushort(l0);
                int off = kk * PITCH_B + pp * 2;
                *(uint32_t*)(sm + S_BHI + off) = hp;
                *(uint32_t*)(sm + S_BLO + off) = lp;
            }
            cp_async_wait_all();
            __syncthreads();

            // ---- MMA: 2 k16 steps x (2 mt x 8 nt x 3 split terms)
#pragma unroll
            for (int s = 0; s < 2; ++s) {
                uint32_t ah[2][4], al[2][4];
#pragma unroll
                for (int mt = 0; mt < 2; ++mt) {
                    int row = m0 + mt * 16 + (lane & 15);
                    uint32_t ao = row * PITCH_A + s * 32 + ((lane >> 4) << 4);
                    ldsm4(ah[mt], sb + S_AHI + ao);
                    ldsm4(al[mt], sb + S_ALO + ao);
                }
#pragma unroll
                for (int ng = 0; ng < 4; ++ng) {
                    int k = s * 16 + (lane & 15);
                    int ncol = n0 + ng * 16 + ((lane >> 4) << 3);
                    uint32_t bo = k * PITCH_B + ncol * 2;
                    uint32_t bh[4], bl[4];
                    ldsm4t(bh, sb + S_BHI + bo);
                    ldsm4t(bl, sb + S_BLO + bo);
#pragma unroll
                    for (int mt = 0; mt < 2; ++mt)
#pragma unroll
                        for (int j = 0; j < 2; ++j) {
                            float* c = acc[mt][2 * ng + j];
                            mma16816(c, ah[mt], &bh[2 * j]);
                            mma16816(c, ah[mt], &bl[2 * j]);
                            mma16816(c, al[mt], &bh[2 * j]);
                        }
                }
            }
        }
    }

    // ---- epilogue: BN (+relu) + mask (+vector / +residual) ----
#pragma unroll
    for (int mt = 0; mt < 2; ++mt) {
#pragma unroll
        for (int hr = 0; hr < 2; ++hr) {
            int ml = m0 + mt * 16 + (lane >> 2) + hr * 8;
            int ch = half * 128 + ml;
            float s  = scs[ml];
            float b2 = bis[ml];
            float vv = (STAGE == 1) ? vec[b * C_ + ch] : 0.f;
            size_t chb = (size_t)b * CHW_ + (size_t)ch * HW_;
#pragma unroll
            for (int nt = 0; nt < 8; ++nt) {
                int pix = pixbase + n0 + nt * 8 + (lane & 3) * 2;
#pragma unroll
                for (int q = 0; q < 2; ++q) {
                    int p = pix + q;
                    if (p < HW_) {
                        float val = acc[mt][nt][hr * 2 + q] * s + b2;
                        float mk = mask[(size_t)b * HW_ + p];
                        if (STAGE == 1)
                            g_scratch[chb + p] = mk * vv * fmaxf(val, 0.f);
                        else
                            out[chb + p] = fmaxf(x[chb + p] + mk * val, 0.f);
                    }
                }
            }
        }
    }
}

extern "C" void kernel_launch(void* const* d_in, const int* in_sizes, int n_in,
                              void* d_out, int out_size) {
    const float* x    = (const float*)d_in[0];
    const float* mask = (const float*)d_in[1];
    const float* md   = (const float*)d_in[2];
    const float* vec  = (const float*)d_in[3];
    const float* w1   = (const float*)d_in[4];
    const float* g1   = (const float*)d_in[5];
    const float* b1   = (const float*)d_in[6];
    const float* m1   = (const float*)d_in[7];
    const float* v1   = (const float*)d_in[8];
    const float* w2   = (const float*)d_in[9];
    const float* g2   = (const float*)d_in[10];
    const float* b2   = (const float*)d_in[11];
    const float* m2   = (const float*)d_in[12];
    const float* v2   = (const float*)d_in[13];
    float* out = (float*)d_out;

    prepack_kernel<<<4608, 256>>>(w1, w2);          // 288 tiles * 4096 elems / 256
    dim3 grid(2, 25, B_);                            // half, pixel-block, batch
    conv_hmma<1><<<grid, 256>>>(x, md, mask, vec, g1, b1, m1, v1, nullptr);
    conv_hmma<2><<<grid, 256>>>(x, nullptr, mask, nullptr, g2, b2, m2, v2, out);
}

// round 8
// speedup vs baseline: 5.0381x; 1.4764x over previous
#include <cuda_runtime.h>
#include <cuda_bf16.h>
#include <cstdint>

// Sparse BasicBlock via HMMA (mma.sync bf16, sm_80-compatible path).
// Base = validated Round-3 kernel (rel_err 1.06e-5), plus ONE exact lever:
// active-pixel compaction. GEMM columns are only the pixels with mask==1;
// inactive pixels get out = relu(x) and g = 0 from a fill prepass (exact:
// reference out = relu(x + h*mask) = relu(x) there, and conv2's input is
// zero at inactive pixels). All inner machinery (gather with mask_dilate
// premultiply, bf16 3-term split, ldmatrix/mma layout, pipeline) unchanged.

namespace {
constexpr int B_ = 32, C_ = 256, H_ = 56, W_ = 56;
constexpr int HW_ = H_ * W_, CHW_ = C_ * HW_;
constexpr float EPS = 1e-5f;

constexpr int PITCH_A = 80;              // 32 bf16 = 64B data + 16B pad
constexpr int PITCH_B = 272;             // 128 bf16 = 256B data + 16B pad
constexpr int A_TILE  = 128 * PITCH_A;   // 10240 B (one matrix)
constexpr int TILE_BYTES = 2 * A_TILE;   // hi+lo weight tile image = 20480 B
constexpr int B_TILE  = 32 * PITCH_B;    // 8704 B

// smem offsets
constexpr int S_AHI = 0;
constexpr int S_BHI = TILE_BYTES;                // 20480
constexpr int S_BLO = S_BHI + B_TILE;            // 29184
constexpr int S_SC  = S_BLO + B_TILE;            // 37888 (128 f32)
constexpr int S_BI  = S_SC + 512;                // 38400
constexpr int S_LIST = S_BI + 512;               // 38912 (128 int)
constexpr int SMEM_BYTES = S_LIST + 512;         // 39424 (< 48K static)
constexpr int LSTRIDE = 3200;
}

__device__ float g_scratch[(size_t)B_ * CHW_];                       // 103 MB
__device__ __align__(16) unsigned char wpack[(size_t)288 * TILE_BYTES]; // 5.9 MB
__device__ int d_cnt[B_];
__device__ int d_list[B_ * LSTRIDE];

// ---------------- helpers ----------------
__device__ __forceinline__ uint32_t smem_u32(const void* p) {
    uint32_t a;
    asm("{ .reg .u64 t; cvta.to.shared.u64 t, %1; cvt.u32.u64 %0, t; }" : "=r"(a) : "l"(p));
    return a;
}
__device__ __forceinline__ void cp_async16(uint32_t s, const void* g) {
    asm volatile("cp.async.cg.shared.global [%0], [%1], 16;" :: "r"(s), "l"(g));
}
__device__ __forceinline__ void cp_async_wait_all() {
    asm volatile("cp.async.commit_group;\ncp.async.wait_group 0;" ::: "memory");
}
__device__ __forceinline__ void ldsm4(uint32_t* r, uint32_t a) {
    asm volatile("ldmatrix.sync.aligned.m8n8.x4.shared.b16 {%0,%1,%2,%3}, [%4];"
                 : "=r"(r[0]), "=r"(r[1]), "=r"(r[2]), "=r"(r[3]) : "r"(a));
}
__device__ __forceinline__ void ldsm4t(uint32_t* r, uint32_t a) {
    asm volatile("ldmatrix.sync.aligned.m8n8.x4.trans.shared.b16 {%0,%1,%2,%3}, [%4];"
                 : "=r"(r[0]), "=r"(r[1]), "=r"(r[2]), "=r"(r[3]) : "r"(a));
}
__device__ __forceinline__ void mma16816(float* c, const uint32_t* a, const uint32_t* b) {
    asm volatile(
        "mma.sync.aligned.m16n8k16.row.col.f32.bf16.bf16.f32 "
        "{%0,%1,%2,%3}, {%4,%5,%6,%7}, {%8,%9}, {%0,%1,%2,%3};"
        : "+f"(c[0]), "+f"(c[1]), "+f"(c[2]), "+f"(c[3])
        : "r"(a[0]), "r"(a[1]), "r"(a[2]), "r"(a[3]), "r"(b[0]), "r"(b[1]));
}
// -----------------------------------------

// Pre-pack weights [O][I][3][3] fp32 into per-(conv,half,tap,chunk) smem tile
// images: hi matrix [128 rows x 80B pitch] then lo, bf16.  (verbatim R3)
__global__ __launch_bounds__(256) void prepack_kernel(const float* __restrict__ w1,
                                                      const float* __restrict__ w2) {
    size_t idx = (size_t)blockIdx.x * 256 + threadIdx.x;   // 288 * 4096
    int tix = (int)(idx >> 12);
    int e   = (int)(idx & 4095);
    int m = e >> 5, kk = e & 31;
    int chunk = tix & 7, tap = (tix >> 3) % 9;
    int nh = (tix / 72) & 1, conv = tix / 144;
    const float* w = conv ? w2 : w1;
    float v = w[((size_t)(nh * 128 + m) * C_ + (chunk * 32 + kk)) * 9 + tap];
    __nv_bfloat16 h = __float2bfloat16(v);
    __nv_bfloat16 l = __float2bfloat16(v - __bfloat162float(h));
    unsigned char* base = wpack + (size_t)tix * TILE_BYTES + m * PITCH_A + kk * 2;
    *(__nv_bfloat16*)base = h;
    *(__nv_bfloat16*)(base + A_TILE) = l;
}

// Active-pixel compaction (list order irrelevant: per-pixel results independent).
__global__ void compact_kernel(const float* __restrict__ mask) {
    int b = blockIdx.x;
    __shared__ int cnt;
    if (threadIdx.x == 0) cnt = 0;
    __syncthreads();
    for (int p = threadIdx.x; p < HW_; p += 256)
        if (mask[(size_t)b * HW_ + p] > 0.5f) {
            int s = atomicAdd(&cnt, 1);
            d_list[b * LSTRIDE + s] = p;
        }
    __syncthreads();
    if (threadIdx.x == 0) d_cnt[b] = cnt;
}

// Inactive pixels: out = relu(x), g_scratch = 0.
__global__ __launch_bounds__(256) void fill_kernel(const float* __restrict__ x,
                                                   const float* __restrict__ mask,
                                                   float* __restrict__ out) {
    int idx = blockIdx.x * 256 + threadIdx.x;     // < CHW_ (3136 * 256 exactly)
    int b = blockIdx.y;
    int p = idx % HW_;
    if (mask[(size_t)b * HW_ + p] < 0.5f) {
        size_t i = (size_t)b * CHW_ + idx;
        out[i] = fmaxf(x[i], 0.f);
        g_scratch[i] = 0.f;
    }
}

// STAGE 1: in = x*mask_dilate -> g_scratch   STAGE 2: in = g_scratch -> out
template <int STAGE>
__global__ __launch_bounds__(256, 2)
void conv_hmma(const float* __restrict__ x, const float* __restrict__ md,
               const float* __restrict__ vec,
               const float* __restrict__ bg, const float* __restrict__ bb,
               const float* __restrict__ bm, const float* __restrict__ bv,
               float* __restrict__ out)
{
    __shared__ __align__(16) unsigned char sm[SMEM_BYTES];
    const uint32_t sb = smem_u32(sm);
    const int t = threadIdx.x, lane = t & 31, wid = t >> 5;
    const int nh = blockIdx.x, blk = blockIdx.y, b = blockIdx.z;
    const int cnt = d_cnt[b];
    const int pixbase = blk * 128;
    if (pixbase >= cnt) return;            // uniform per CTA

    float* scs = (float*)(sm + S_SC);
    float* bis = (float*)(sm + S_BI);
    int* slist = (int*)(sm + S_LIST);
    if (t < 128) {
        int ch = nh * 128 + t;
        float iv = rsqrtf(bv[ch] + EPS) * bg[ch];
        scs[t] = iv;
        bis[t] = bb[ch] - bm[ch] * iv;
        int i0 = pixbase + t;
        slist[t] = (i0 < cnt) ? d_list[b * LSTRIDE + i0] : -1;
    }
    __syncthreads();

    const float* inb = (STAGE == 1) ? x + (size_t)b * CHW_ : g_scratch + (size_t)b * CHW_;
    const float* mdb = (STAGE == 1) ? md + (size_t)b * HW_ : nullptr;

    // B gather geometry: each thread owns one (compacted) pixel pair
    const int pp  = (t & 63) * 2;            // local column pair base
    const int kk0 = t >> 6;                  // 0..3
    const int p0r = slist[pp], p1r = slist[pp + 1];
    const bool pv0 = p0r >= 0, pv1 = p1r >= 0;
    const int p0 = pv0 ? p0r : 0, p1 = pv1 ? p1r : 0;
    const int py0 = p0 / W_, px0 = p0 - py0 * W_;
    const int py1 = p1 / W_, px1 = p1 - py1 * W_;

    // warp tiling: 4 (ch) x 2 (pix)
    const int m0 = (wid & 3) * 32;           // channel row base within 128
    const int n0 = (wid >> 2) * 64;          // pixel col base within 128

    float acc[2][8][4];
#pragma unroll
    for (int mt = 0; mt < 2; ++mt)
#pragma unroll
        for (int nt = 0; nt < 8; ++nt)
#pragma unroll
            for (int q = 0; q < 4; ++q) acc[mt][nt][q] = 0.f;

    const int tixbase = ((STAGE - 1) * 2 + nh) * 72;

    for (int tap = 0; tap < 9; ++tap) {
        const int dy = tap / 3 - 1, dx = tap % 3 - 1;
        const int iy0 = py0 + dy, ix0 = px0 + dx;
        const int iy1 = py1 + dy, ix1 = px1 + dx;
        const bool v0 = pv0 && (unsigned)iy0 < (unsigned)H_ && (unsigned)ix0 < (unsigned)W_;
        const bool v1 = pv1 && (unsigned)iy1 < (unsigned)H_ && (unsigned)ix1 < (unsigned)W_;
        const int sp0 = v0 ? iy0 * W_ + ix0 : 0;
        const int sp1 = v1 ? iy1 * W_ + ix1 : 0;
        float pm0 = 0.f, pm1 = 0.f;
        if (v0) pm0 = (STAGE == 1) ? mdb[sp0] : 1.f;
        if (v1) pm1 = (STAGE == 1) ? mdb[sp1] : 1.f;

        for (int chunk = 0; chunk < 8; ++chunk) {
            __syncthreads();   // previous iter's MMAs done before overwriting tiles

            // ---- A (weights): cp.async copy of the prepacked 20480B tile image
            {
                const unsigned char* g =
                    wpack + (size_t)(tixbase + tap * 8 + chunk) * TILE_BYTES;
#pragma unroll
                for (int i = 0; i < 5; ++i) {
                    int off = (t + 256 * i) * 16;
                    cp_async16(sb + S_AHI + off, g + off);
                }
            }
            // ---- B (pixels): gather + premask + bf16 hi/lo split, STS
#pragma unroll
            for (int i = 0; i < 8; ++i) {
                int kk = kk0 + i * 4;
                const float* src = inb + (size_t)(chunk * 32 + kk) * HW_;
                float f0 = v0 ? src[sp0] * pm0 : 0.f;
                float f1 = v1 ? src[sp1] * pm1 : 0.f;
                __nv_bfloat16 h0 = __float2bfloat16(f0), h1 = __float2bfloat16(f1);
                __nv_bfloat16 l0 = __float2bfloat16(f0 - __bfloat162float(h0));
                __nv_bfloat16 l1 = __float2bfloat16(f1 - __bfloat162float(h1));
                uint32_t hp = ((uint32_t)__bfloat16_as_ushort(h1) << 16) | __bfloat16_as_ushort(h0);
                uint32_t lp = ((uint32_t)__bfloat16_as_ushort(l1) << 16) | __bfloat16_as_ushort(l0);
                int off = kk * PITCH_B + pp * 2;
                *(uint32_t*)(sm + S_BHI + off) = hp;
                *(uint32_t*)(sm + S_BLO + off) = lp;
            }
            cp_async_wait_all();
            __syncthreads();

            // ---- MMA: 2 k16 steps x (2 mt x 8 nt x 3 split terms)
#pragma unroll
            for (int s = 0; s < 2; ++s) {
                uint32_t ah[2][4], al[2][4];
#pragma unroll
                for (int mt = 0; mt < 2; ++mt) {
                    int row = m0 + mt * 16 + (lane & 15);
                    uint32_t ao = row * PITCH_A + s * 32 + ((lane >> 4) << 4);
                    ldsm4(ah[mt], sb + S_AHI + ao);
                    ldsm4(al[mt], sb + S_AHI + A_TILE + ao);
                }
#pragma unroll
                for (int ng = 0; ng < 4; ++ng) {
                    int k = s * 16 + (lane & 15);
                    int ncol = n0 + ng * 16 + ((lane >> 4) << 3);
                    uint32_t bo = k * PITCH_B + ncol * 2;
                    uint32_t bh[4], bl[4];
                    ldsm4t(bh, sb + S_BHI + bo);
                    ldsm4t(bl, sb + S_BLO + bo);
#pragma unroll
                    for (int mt = 0; mt < 2; ++mt)
#pragma unroll
                        for (int j = 0; j < 2; ++j) {
                            float* c = acc[mt][2 * ng + j];
                            mma16816(c, ah[mt], &bh[2 * j]);
                            mma16816(c, ah[mt], &bl[2 * j]);
                            mma16816(c, al[mt], &bh[2 * j]);
                        }
                }
            }
        }
    }

    // ---- epilogue: BN (+relu/vector | +residual/relu); mask==1 on all listed
    // pixels, so the reference's mk multiply is the constant 1 here (exact).
#pragma unroll
    for (int mt = 0; mt < 2; ++mt) {
#pragma unroll
        for (int hr = 0; hr < 2; ++hr) {
            int ml = m0 + mt * 16 + (lane >> 2) + hr * 8;
            int ch = nh * 128 + ml;
            float s  = scs[ml];
            float b2 = bis[ml];
            float vv = (STAGE == 1) ? vec[b * C_ + ch] : 0.f;
            size_t chb = (size_t)b * CHW_ + (size_t)ch * HW_;
#pragma unroll
            for (int nt = 0; nt < 8; ++nt) {
#pragma unroll
                for (int q = 0; q < 2; ++q) {
                    int col = n0 + nt * 8 + (lane & 3) * 2 + q;
                    int p = slist[col];
                    if (p >= 0) {
                        float val = acc[mt][nt][hr * 2 + q] * s + b2;
                        if (STAGE == 1)
                            g_scratch[chb + p] = vv * fmaxf(val, 0.f);
                        else
                            out[chb + p] = fmaxf(x[chb + p] + val, 0.f);
                    }
                }
            }
        }
    }
}

extern "C" void kernel_launch(void* const* d_in, const int* in_sizes, int n_in,
                              void* d_out, int out_size) {
    const float* x    = (const float*)d_in[0];
    const float* mask = (const float*)d_in[1];
    const float* md   = (const float*)d_in[2];
    const float* vec  = (const float*)d_in[3];
    const float* w1   = (const float*)d_in[4];
    const float* g1   = (const float*)d_in[5];
    const float* b1   = (const float*)d_in[6];
    const float* m1   = (const float*)d_in[7];
    const float* v1   = (const float*)d_in[8];
    const float* w2   = (const float*)d_in[9];
    const float* g2   = (const float*)d_in[10];
    const float* b2   = (const float*)d_in[11];
    const float* m2   = (const float*)d_in[12];
    const float* v2   = (const float*)d_in[13];
    float* out = (float*)d_out;

    prepack_kernel<<<4608, 256>>>(w1, w2);          // 288 tiles * 4096 elems / 256
    compact_kernel<<<B_, 256>>>(mask);
    {
        dim3 g(CHW_ / 256, B_);
        fill_kernel<<<g, 256>>>(x, mask, out);
    }
    dim3 grid(2, 25, B_);                            // half, pixel-block, batch
    conv_hmma<1><<<grid, 256>>>(x, md, vec, g1, b1, m1, v1, nullptr);
    conv_hmma<2><<<grid, 256>>>(x, nullptr, nullptr, g2, b2, m2, v2, out);
}

// round 10
// speedup vs baseline: 6.2866x; 1.2478x over previous
#include <cuda_runtime.h>
#include <cuda_fp16.h>
#include <cstdint>

// Sparse BasicBlock via fp16 HMMA (mma.sync, sm_80-compatible path).
// Base = validated Round-8 kernel (rel_err 1.06e-5, 1249us) with ONE change:
// bf16 3-term split -> fp16 2-term split (A = hi+lo fp16, B = single fp16).
// Everything else (compaction, gather with mask_dilate premultiply, fp32
// g_scratch, pipeline, ldmatrix/mma addressing) is byte-identical to R8.

namespace {
constexpr int B_ = 32, C_ = 256, H_ = 56, W_ = 56;
constexpr int HW_ = H_ * W_, CHW_ = C_ * HW_;
constexpr float EPS = 1e-5f;

constexpr int PITCH_A = 80;              // 32 fp16 = 64B data + 16B pad
constexpr int PITCH_B = 272;             // 128 fp16 = 256B data + 16B pad
constexpr int A_TILE  = 128 * PITCH_A;   // 10240 B (one matrix)
constexpr int TILE_BYTES = 2 * A_TILE;   // hi+lo weight tile image = 20480 B
constexpr int B_TILE  = 32 * PITCH_B;    // 8704 B

// smem offsets (single B matrix now)
constexpr int S_AHI = 0;
constexpr int S_BHI = TILE_BYTES;                // 20480
constexpr int S_SC  = S_BHI + B_TILE;            // 29184 (128 f32)
constexpr int S_BI  = S_SC + 512;                // 29696
constexpr int S_LIST = S_BI + 512;               // 30208 (128 int)
constexpr int SMEM_BYTES = S_LIST + 512;         // 30720 (< 48K static)
constexpr int LSTRIDE = 3200;
}

__device__ float g_scratch[(size_t)B_ * CHW_];                       // 103 MB
__device__ __align__(16) unsigned char wpack[(size_t)288 * TILE_BYTES]; // 5.9 MB
__device__ int d_cnt[B_];
__device__ int d_list[B_ * LSTRIDE];

// ---------------- helpers ----------------
__device__ __forceinline__ uint32_t smem_u32(const void* p) {
    uint32_t a;
    asm("{ .reg .u64 t; cvta.to.shared.u64 t, %1; cvt.u32.u64 %0, t; }" : "=r"(a) : "l"(p));
    return a;
}
__device__ __forceinline__ void cp_async16(uint32_t s, const void* g) {
    asm volatile("cp.async.cg.shared.global [%0], [%1], 16;" :: "r"(s), "l"(g));
}
__device__ __forceinline__ void cp_async_wait_all() {
    asm volatile("cp.async.commit_group;\ncp.async.wait_group 0;" ::: "memory");
}
__device__ __forceinline__ void ldsm4(uint32_t* r, uint32_t a) {
    asm volatile("ldmatrix.sync.aligned.m8n8.x4.shared.b16 {%0,%1,%2,%3}, [%4];"
                 : "=r"(r[0]), "=r"(r[1]), "=r"(r[2]), "=r"(r[3]) : "r"(a));
}
__device__ __forceinline__ void ldsm4t(uint32_t* r, uint32_t a) {
    asm volatile("ldmatrix.sync.aligned.m8n8.x4.trans.shared.b16 {%0,%1,%2,%3}, [%4];"
                 : "=r"(r[0]), "=r"(r[1]), "=r"(r[2]), "=r"(r[3]) : "r"(a));
}
__device__ __forceinline__ void mma16816(float* c, const uint32_t* a, const uint32_t* b) {
    asm volatile(
        "mma.sync.aligned.m16n8k16.row.col.f32.f16.f16.f32 "
        "{%0,%1,%2,%3}, {%4,%5,%6,%7}, {%8,%9}, {%0,%1,%2,%3};"
        : "+f"(c[0]), "+f"(c[1]), "+f"(c[2]), "+f"(c[3])
        : "r"(a[0]), "r"(a[1]), "r"(a[2]), "r"(a[3]), "r"(b[0]), "r"(b[1]));
}
// -----------------------------------------

// Pre-pack weights [O][I][3][3] fp32 into per-(conv,half,tap,chunk) smem tile
// images: hi matrix [128 rows x 80B pitch] then lo, fp16.
__global__ __launch_bounds__(256) void prepack_kernel(const float* __restrict__ w1,
                                                      const float* __restrict__ w2) {
    size_t idx = (size_t)blockIdx.x * 256 + threadIdx.x;   // 288 * 4096
    int tix = (int)(idx >> 12);
    int e   = (int)(idx & 4095);
    int m = e >> 5, kk = e & 31;
    int chunk = tix & 7, tap = (tix >> 3) % 9;
    int nh = (tix / 72) & 1, conv = tix / 144;
    const float* w = conv ? w2 : w1;
    float v = w[((size_t)(nh * 128 + m) * C_ + (chunk * 32 + kk)) * 9 + tap];
    __half h = __float2half(v);
    __half l = __float2half(v - __half2float(h));
    unsigned char* base = wpack + (size_t)tix * TILE_BYTES + m * PITCH_A + kk * 2;
    *(__half*)base = h;
    *(__half*)(base + A_TILE) = l;
}

// Active-pixel compaction (list order irrelevant: per-pixel results independent).
__global__ void compact_kernel(const float* __restrict__ mask) {
    int b = blockIdx.x;
    __shared__ int cnt;
    if (threadIdx.x == 0) cnt = 0;
    __syncthreads();
    for (int p = threadIdx.x; p < HW_; p += 256)
        if (mask[(size_t)b * HW_ + p] > 0.5f) {
            int s = atomicAdd(&cnt, 1);
            d_list[b * LSTRIDE + s] = p;
        }
    __syncthreads();
    if (threadIdx.x == 0) d_cnt[b] = cnt;
}

// Inactive pixels: out = relu(x), g_scratch = 0.
__global__ __launch_bounds__(256) void fill_kernel(const float* __restrict__ x,
                                                   const float* __restrict__ mask,
                                                   float* __restrict__ out) {
    int idx = blockIdx.x * 256 + threadIdx.x;     // < CHW_ (3136 * 256 exactly)
    int b = blockIdx.y;
    int p = idx % HW_;
    if (mask[(size_t)b * HW_ + p] < 0.5f) {
        size_t i = (size_t)b * CHW_ + idx;
        out[i] = fmaxf(x[i], 0.f);
        g_scratch[i] = 0.f;
    }
}

// STAGE 1: in = x*mask_dilate -> g_scratch   STAGE 2: in = g_scratch -> out
template <int STAGE>
__global__ __launch_bounds__(256, 2)
void conv_hmma(const float* __restrict__ x, const float* __restrict__ md,
               const float* __restrict__ vec,
               const float* __restrict__ bg, const float* __restrict__ bb,
               const float* __restrict__ bm, const float* __restrict__ bv,
               float* __restrict__ out)
{
    __shared__ __align__(16) unsigned char sm[SMEM_BYTES];
    const uint32_t sb = smem_u32(sm);
    const int t = threadIdx.x, lane = t & 31, wid = t >> 5;
    const int nh = blockIdx.x, blk = blockIdx.y, b = blockIdx.z;
    const int cnt = d_cnt[b];
    const int pixbase = blk * 128;
    if (pixbase >= cnt) return;            // uniform per CTA

    float* scs = (float*)(sm + S_SC);
    float* bis = (float*)(sm + S_BI);
    int* slist = (int*)(sm + S_LIST);
    if (t < 128) {
        int ch = nh * 128 + t;
        float iv = rsqrtf(bv[ch] + EPS) * bg[ch];
        scs[t] = iv;
        bis[t] = bb[ch] - bm[ch] * iv;
        int i0 = pixbase + t;
        slist[t] = (i0 < cnt) ? d_list[b * LSTRIDE + i0] : -1;
    }
    __syncthreads();

    const float* inb = (STAGE == 1) ? x + (size_t)b * CHW_ : g_scratch + (size_t)b * CHW_;
    const float* mdb = (STAGE == 1) ? md + (size_t)b * HW_ : nullptr;

    // B gather geometry: each thread owns one (compacted) pixel pair
    const int pp  = (t & 63) * 2;            // local column pair base
    const int kk0 = t >> 6;                  // 0..3
    const int p0r = slist[pp], p1r = slist[pp + 1];
    const bool pv0 = p0r >= 0, pv1 = p1r >= 0;
    const int p0 = pv0 ? p0r : 0, p1 = pv1 ? p1r : 0;
    const int py0 = p0 / W_, px0 = p0 - py0 * W_;
    const int py1 = p1 / W_, px1 = p1 - py1 * W_;

    // warp tiling: 4 (ch) x 2 (pix)
    const int m0 = (wid & 3) * 32;           // channel row base within 128
    const int n0 = (wid >> 2) * 64;          // pixel col base within 128

    float acc[2][8][4];
#pragma unroll
    for (int mt = 0; mt < 2; ++mt)
#pragma unroll
        for (int nt = 0; nt < 8; ++nt)
#pragma unroll
            for (int q = 0; q < 4; ++q) acc[mt][nt][q] = 0.f;

    const int tixbase = ((STAGE - 1) * 2 + nh) * 72;

    for (int tap = 0; tap < 9; ++tap) {
        const int dy = tap / 3 - 1, dx = tap % 3 - 1;
        const int iy0 = py0 + dy, ix0 = px0 + dx;
        const int iy1 = py1 + dy, ix1 = px1 + dx;
        const bool v0 = pv0 && (unsigned)iy0 < (unsigned)H_ && (unsigned)ix0 < (unsigned)W_;
        const bool v1 = pv1 && (unsigned)iy1 < (unsigned)H_ && (unsigned)ix1 < (unsigned)W_;
        const int sp0 = v0 ? iy0 * W_ + ix0 : 0;
        const int sp1 = v1 ? iy1 * W_ + ix1 : 0;
        float pm0 = 0.f, pm1 = 0.f;
        if (v0) pm0 = (STAGE == 1) ? mdb[sp0] : 1.f;
        if (v1) pm1 = (STAGE == 1) ? mdb[sp1] : 1.f;

        for (int chunk = 0; chunk < 8; ++chunk) {
            __syncthreads();   // previous iter's MMAs done before overwriting tiles

            // ---- A (weights): cp.async copy of the prepacked 20480B tile image
            {
                const unsigned char* g =
                    wpack + (size_t)(tixbase + tap * 8 + chunk) * TILE_BYTES;
#pragma unroll
                for (int i = 0; i < 5; ++i) {
                    int off = (t + 256 * i) * 16;
                    cp_async16(sb + S_AHI + off, g + off);
                }
            }
            // ---- B (pixels): gather + premask + single fp16, STS
#pragma unroll
            for (int i = 0; i < 8; ++i) {
                int kk = kk0 + i * 4;
                const float* src = inb + (size_t)(chunk * 32 + kk) * HW_;
                float f0 = v0 ? src[sp0] * pm0 : 0.f;
                float f1 = v1 ? src[sp1] * pm1 : 0.f;
                __half h0 = __float2half(f0), h1 = __float2half(f1);
                uint32_t hp = ((uint32_t)__half_as_ushort(h1) << 16) | __half_as_ushort(h0);
                int off = kk * PITCH_B + pp * 2;
                *(uint32_t*)(sm + S_BHI + off) = hp;
            }
            cp_async_wait_all();
            __syncthreads();

            // ---- MMA: 2 k16 steps x (2 mt x 8 nt x 2 split terms)
#pragma unroll
            for (int s = 0; s < 2; ++s) {
                uint32_t ah[2][4], al[2][4];
#pragma unroll
                for (int mt = 0; mt < 2; ++mt) {
                    int row = m0 + mt * 16 + (lane & 15);
                    uint32_t ao = row * PITCH_A + s * 32 + ((lane >> 4) << 4);
                    ldsm4(ah[mt], sb + S_AHI + ao);
                    ldsm4(al[mt], sb + S_AHI + A_TILE + ao);
                }
#pragma unroll
                for (int ng = 0; ng < 4; ++ng) {
                    int k = s * 16 + (lane & 15);
                    int ncol = n0 + ng * 16 + ((lane >> 4) << 3);
                    uint32_t bo = k * PITCH_B + ncol * 2;
                    uint32_t bh[4];
                    ldsm4t(bh, sb + S_BHI + bo);
#pragma unroll
                    for (int mt = 0; mt < 2; ++mt)
#pragma unroll
                        for (int j = 0; j < 2; ++j) {
                            float* c = acc[mt][2 * ng + j];
                            mma16816(c, ah[mt], &bh[2 * j]);
                            mma16816(c, al[mt], &bh[2 * j]);
                        }
                }
            }
        }
    }

    // ---- epilogue: BN (+relu/vector | +residual/relu); mask==1 on all listed
    // pixels, so the reference's mk multiply is the constant 1 here (exact).
#pragma unroll
    for (int mt = 0; mt < 2; ++mt) {
#pragma unroll
        for (int hr = 0; hr < 2; ++hr) {
            int ml = m0 + mt * 16 + (lane >> 2) + hr * 8;
            int ch = nh * 128 + ml;
            float s  = scs[ml];
            float b2 = bis[ml];
            float vv = (STAGE == 1) ? vec[b * C_ + ch] : 0.f;
            size_t chb = (size_t)b * CHW_ + (size_t)ch * HW_;
#pragma unroll
            for (int nt = 0; nt < 8; ++nt) {
#pragma unroll
                for (int q = 0; q < 2; ++q) {
                    int col = n0 + nt * 8 + (lane & 3) * 2 + q;
                    int p = slist[col];
                    if (p >= 0) {
                        float val = acc[mt][nt][hr * 2 + q] * s + b2;
                        if (STAGE == 1)
                            g_scratch[chb + p] = vv * fmaxf(val, 0.f);
                        else
                            out[chb + p] = fmaxf(x[chb + p] + val, 0.f);
                    }
                }
            }
        }
    }
}

extern "C" void kernel_launch(void* const* d_in, const int* in_sizes, int n_in,
                              void* d_out, int out_size) {
    const float* x    = (const float*)d_in[0];
    const float* mask = (const float*)d_in[1];
    const float* md   = (const float*)d_in[2];
    const float* vec  = (const float*)d_in[3];
    const float* w1   = (const float*)d_in[4];
    const float* g1   = (const float*)d_in[5];
    const float* b1   = (const float*)d_in[6];
    const float* m1   = (const float*)d_in[7];
    const float* v1   = (const float*)d_in[8];
    const float* w2   = (const float*)d_in[9];
    const float* g2   = (const float*)d_in[10];
    const float* b2   = (const float*)d_in[11];
    const float* m2   = (const float*)d_in[12];
    const float* v2   = (const float*)d_in[13];
    float* out = (float*)d_out;

    prepack_kernel<<<4608, 256>>>(w1, w2);          // 288 tiles * 4096 elems / 256
    compact_kernel<<<B_, 256>>>(mask);
    {
        dim3 g(CHW_ / 256, B_);
        fill_kernel<<<g, 256>>>(x, mask, out);
    }
    dim3 grid(2, 25, B_);                            // half, pixel-block, batch
    conv_hmma<1><<<grid, 256>>>(x, md, vec, g1, b1, m1, v1, nullptr);
    conv_hmma<2><<<grid, 256>>>(x, nullptr, nullptr, g2, b2, m2, v2, out);
}